// round 1
// baseline (speedup 1.0000x reference)
#include <cuda_runtime.h>
#include <math.h>

// Problem constants
#define DM   768     // d_model
#define DI   1536    // d_inner
#define DR   48      // dt_rank
#define DS   16      // d_state
#define SEQL 2048    // L
#define XPW  80      // DT_RANK + 2*D_STATE
#define XPWP 128     // padded width
#define LCH  32      // chunk length
#define NCH  64      // number of chunks (64*32 = 2048)

// ---------------- scratch (device globals; no allocation allowed) ----------
__device__ float d_xr[SEQL * 2 * DI];        // in_proj output [L, 3072]
__device__ float d_xs[SEQL * DI];            // conv+silu output (u)
__device__ float d_xprojw_pad[DI * XPWP];    // x_proj_w padded to 128 cols
__device__ float d_xdbl[SEQL * XPWP];        // x_dbl padded [L, 128]
__device__ float d_delta[SEQL * DI];         // softplus(dt) [L, 1536]
__device__ float d_S[NCH * DI];              // per-chunk delta sums
__device__ float d_hpart[NCH * DI * DS];     // per-chunk partial final states
__device__ float d_hin[NCH * DI * DS];       // per-chunk incoming states
__device__ float d_gated[SEQL * DI];         // (scan_out + u*D) * silu(res)

// ---------------- generic register-tiled SGEMM -----------------------------
// C[M,N] = A[M,K(lda)] * B[K,N]   (all row-major, dims divisible by tiles)
// MODE 0: plain.  MODE 1: +bias then softplus (for delta).
template<int BM, int BN, int BK, int TM, int TN, int MODE>
__global__ __launch_bounds__((BM / TM) * (BN / TN))
void sgemm_kernel(int M, int N, int K, int lda,
                  const float* __restrict__ A,
                  const float* __restrict__ B,
                  const float* __restrict__ bias,
                  float* __restrict__ C)
{
    constexpr int THREADS = (BM / TM) * (BN / TN);
    __shared__ __align__(16) float As[BK][BM];
    __shared__ __align__(16) float Bs[BK][BN];

    const int tid = threadIdx.x;
    const int bx = blockIdx.x, by = blockIdx.y;
    const int tcol = tid % (BN / TN);
    const int trow = tid / (BN / TN);

    const float* Ab = A + (size_t)by * BM * lda;
    const float* Bb = B + (size_t)bx * BN;
    float* Cb = C + (size_t)by * BM * N + (size_t)bx * BN;

    float acc[TM][TN];
#pragma unroll
    for (int i = 0; i < TM; i++)
#pragma unroll
        for (int j = 0; j < TN; j++) acc[i][j] = 0.f;

    constexpr int numA4 = BM * BK / 4;
    constexpr int numB4 = BK * BN / 4;

    for (int k0 = 0; k0 < K; k0 += BK) {
        // load A tile (transposed into As[col][row])
#pragma unroll
        for (int i = tid; i < numA4; i += THREADS) {
            int row = i / (BK / 4);
            int cg  = i % (BK / 4);
            float4 v = *reinterpret_cast<const float4*>(Ab + (size_t)row * lda + k0 + cg * 4);
            As[cg * 4 + 0][row] = v.x;
            As[cg * 4 + 1][row] = v.y;
            As[cg * 4 + 2][row] = v.z;
            As[cg * 4 + 3][row] = v.w;
        }
        // load B tile
#pragma unroll
        for (int i = tid; i < numB4; i += THREADS) {
            int row = i / (BN / 4);
            int col = (i % (BN / 4)) * 4;
            *reinterpret_cast<float4*>(&Bs[row][col]) =
                *reinterpret_cast<const float4*>(Bb + (size_t)(k0 + row) * N + col);
        }
        __syncthreads();

        float ar[TM], br[TN];
#pragma unroll
        for (int kk = 0; kk < BK; kk++) {
#pragma unroll
            for (int i = 0; i < TM; i++) ar[i] = As[kk][trow * TM + i];
#pragma unroll
            for (int j = 0; j < TN; j++) br[j] = Bs[kk][tcol * TN + j];
#pragma unroll
            for (int i = 0; i < TM; i++)
#pragma unroll
                for (int j = 0; j < TN; j++) acc[i][j] = fmaf(ar[i], br[j], acc[i][j]);
        }
        __syncthreads();
    }

#pragma unroll
    for (int i = 0; i < TM; i++) {
#pragma unroll
        for (int j = 0; j < TN; j += 4) {
            float4 v;
            float e[4];
#pragma unroll
            for (int q = 0; q < 4; q++) {
                float val = acc[i][j + q];
                if (MODE == 1) {
                    int gcol = bx * BN + tcol * TN + j + q;
                    val += bias[gcol];
                    // stable softplus
                    val = (val > 20.f) ? val : log1pf(expf(val));
                }
                e[q] = val;
            }
            v.x = e[0]; v.y = e[1]; v.z = e[2]; v.w = e[3];
            *reinterpret_cast<float4*>(Cb + (size_t)(trow * TM + i) * N + tcol * TN + j) = v;
        }
    }
}

// ---------------- pad x_proj_w to 128 cols ---------------------------------
__global__ void pad_xprojw_kernel(const float* __restrict__ w)
{
    int idx = blockIdx.x * blockDim.x + threadIdx.x;   // over DI*128
    if (idx >= DI * XPWP) return;
    int k = idx / XPWP, j = idx % XPWP;
    d_xprojw_pad[idx] = (j < XPW) ? w[k * XPW + j] : 0.f;
}

// ---------------- depthwise causal conv (k=4) + bias + SiLU ----------------
__global__ void conv_silu_kernel(const float* __restrict__ conv_w,
                                 const float* __restrict__ conv_b)
{
    int idx = blockIdx.x * blockDim.x + threadIdx.x;   // over L*DI
    if (idx >= SEQL * DI) return;
    int d = idx % DI;
    int l = idx / DI;
    float acc = conv_b[d];
#pragma unroll
    for (int j = 0; j < 4; j++) {
        int ls = l - 3 + j;
        if (ls >= 0)
            acc = fmaf(conv_w[j * DI + d], d_xr[(size_t)ls * (2 * DI) + d], acc);
    }
    // silu
    d_xs[idx] = acc / (1.f + __expf(-acc));
}

// ---------------- scan pass 1: per-chunk partial states --------------------
// grid (DI/256, NCH), block 256. One thread = one channel d, one chunk.
__global__ __launch_bounds__(256) void scan_pass1_kernel(const float* __restrict__ a_log)
{
    const int d  = blockIdx.x * 256 + threadIdx.x;
    const int ck = blockIdx.y;
    const int l0 = ck * LCH;

    __shared__ __align__(16) float s_b[LCH * DS];
    for (int i = threadIdx.x; i < LCH * DS; i += 256) {
        int r = i >> 4, n = i & 15;
        s_b[i] = d_xdbl[(size_t)(l0 + r) * XPWP + DR + n];
    }
    __syncthreads();

    float aN[DS];
#pragma unroll
    for (int n = 0; n < DS; n++) aN[n] = -expf(a_log[d * DS + n]);

    float h[DS];
#pragma unroll
    for (int n = 0; n < DS; n++) h[n] = 0.f;
    float Ssum = 0.f;

    for (int l = l0; l < l0 + LCH; l++) {
        float dl = d_delta[(size_t)l * DI + d];
        float u  = d_xs[(size_t)l * DI + d];
        float du = dl * u;
        Ssum += dl;
        const float4* bp = reinterpret_cast<const float4*>(s_b + (l - l0) * DS);
        float4 q0 = bp[0], q1 = bp[1], q2 = bp[2], q3 = bp[3];
        float bb[DS] = {q0.x,q0.y,q0.z,q0.w, q1.x,q1.y,q1.z,q1.w,
                        q2.x,q2.y,q2.z,q2.w, q3.x,q3.y,q3.z,q3.w};
#pragma unroll
        for (int n = 0; n < DS; n++) {
            float e = __expf(dl * aN[n]);
            h[n] = fmaf(e, h[n], du * bb[n]);
        }
    }
    d_S[ck * DI + d] = Ssum;
    float4* hp = reinterpret_cast<float4*>(&d_hpart[((size_t)ck * DI + d) * DS]);
#pragma unroll
    for (int n = 0; n < 4; n++)
        hp[n] = make_float4(h[4*n], h[4*n+1], h[4*n+2], h[4*n+3]);
}

// ---------------- scan pass 2: sequential chunk combine --------------------
// one thread per (d, n); 64-iteration sequential loop.
__global__ __launch_bounds__(256) void scan_combine_kernel(const float* __restrict__ a_log)
{
    int t = blockIdx.x * 256 + threadIdx.x;   // t < DI*DS
    if (t >= DI * DS) return;
    int d = t >> 4;
    float aN = -expf(a_log[t]);
    float h = 0.f;
    for (int ck = 0; ck < NCH; ck++) {
        d_hin[(size_t)ck * DI * DS + t] = h;
        float A = __expf(aN * d_S[ck * DI + d]);
        h = fmaf(A, h, d_hpart[(size_t)ck * DI * DS + t]);
    }
}

// ---------------- scan pass 3: full replay + y + gating --------------------
__global__ __launch_bounds__(256) void scan_pass3_kernel(const float* __restrict__ a_log,
                                                         const float* __restrict__ d_param)
{
    const int d  = blockIdx.x * 256 + threadIdx.x;
    const int ck = blockIdx.y;
    const int l0 = ck * LCH;

    __shared__ __align__(16) float s_b[LCH * DS];
    __shared__ __align__(16) float s_c[LCH * DS];
    for (int i = threadIdx.x; i < LCH * DS; i += 256) {
        int r = i >> 4, n = i & 15;
        s_b[i] = d_xdbl[(size_t)(l0 + r) * XPWP + DR + n];
        s_c[i] = d_xdbl[(size_t)(l0 + r) * XPWP + DR + DS + n];
    }
    __syncthreads();

    float aN[DS];
#pragma unroll
    for (int n = 0; n < DS; n++) aN[n] = -expf(a_log[d * DS + n]);

    float h[DS];
    const float4* hp = reinterpret_cast<const float4*>(&d_hin[((size_t)ck * DI + d) * DS]);
#pragma unroll
    for (int n = 0; n < 4; n++) {
        float4 v = hp[n];
        h[4*n] = v.x; h[4*n+1] = v.y; h[4*n+2] = v.z; h[4*n+3] = v.w;
    }
    const float Dp = d_param[d];

    for (int l = l0; l < l0 + LCH; l++) {
        float dl = d_delta[(size_t)l * DI + d];
        float u  = d_xs[(size_t)l * DI + d];
        float du = dl * u;
        const float4* bp = reinterpret_cast<const float4*>(s_b + (l - l0) * DS);
        const float4* cp = reinterpret_cast<const float4*>(s_c + (l - l0) * DS);
        float4 b0 = bp[0], b1 = bp[1], b2 = bp[2], b3 = bp[3];
        float4 c0 = cp[0], c1 = cp[1], c2 = cp[2], c3 = cp[3];
        float bb[DS] = {b0.x,b0.y,b0.z,b0.w, b1.x,b1.y,b1.z,b1.w,
                        b2.x,b2.y,b2.z,b2.w, b3.x,b3.y,b3.z,b3.w};
        float cc[DS] = {c0.x,c0.y,c0.z,c0.w, c1.x,c1.y,c1.z,c1.w,
                        c2.x,c2.y,c2.z,c2.w, c3.x,c3.y,c3.z,c3.w};
        float y = 0.f;
#pragma unroll
        for (int n = 0; n < DS; n++) {
            float e = __expf(dl * aN[n]);
            h[n] = fmaf(e, h[n], du * bb[n]);
            y = fmaf(h[n], cc[n], y);
        }
        y = fmaf(u, Dp, y);
        float r = d_xr[(size_t)l * (2 * DI) + DI + d];
        float sr = r / (1.f + __expf(-r));
        d_gated[(size_t)l * DI + d] = y * sr;
    }
}

// ---------------- launch ---------------------------------------------------
extern "C" void kernel_launch(void* const* d_in, const int* in_sizes, int n_in,
                              void* d_out, int out_size)
{
    const float* x          = (const float*)d_in[0];
    const float* in_proj_w  = (const float*)d_in[1];
    const float* conv_w     = (const float*)d_in[2];
    const float* conv_b     = (const float*)d_in[3];
    const float* x_proj_w   = (const float*)d_in[4];
    const float* dt_proj_w  = (const float*)d_in[5];
    const float* dt_proj_b  = (const float*)d_in[6];
    const float* a_log      = (const float*)d_in[7];
    const float* d_param    = (const float*)d_in[8];
    const float* out_proj_w = (const float*)d_in[9];
    float* out = (float*)d_out;

    void *p_xr, *p_xs, *p_wpad, *p_xdbl, *p_delta, *p_gated;
    cudaGetSymbolAddress(&p_xr,    d_xr);
    cudaGetSymbolAddress(&p_xs,    d_xs);
    cudaGetSymbolAddress(&p_wpad,  d_xprojw_pad);
    cudaGetSymbolAddress(&p_xdbl,  d_xdbl);
    cudaGetSymbolAddress(&p_delta, d_delta);
    cudaGetSymbolAddress(&p_gated, d_gated);

    // 0) pad x_proj_w -> [1536,128]
    pad_xprojw_kernel<<<(DI * XPWP + 255) / 256, 256>>>(x_proj_w);

    // 1) in_proj: [2048,768] @ [768,3072] -> d_xr
    {
        dim3 grid((2 * DI) / 128, SEQL / 128);
        sgemm_kernel<128,128,8,8,8,0><<<grid, 256>>>(SEQL, 2 * DI, DM, DM,
            x, in_proj_w, nullptr, (float*)p_xr);
    }

    // 2) depthwise conv + SiLU -> d_xs
    conv_silu_kernel<<<(SEQL * DI + 255) / 256, 256>>>(conv_w, conv_b);

    // 3) x_dbl (padded): [2048,1536] @ [1536,128] -> d_xdbl
    {
        dim3 grid(XPWP / 64, SEQL / 64);
        sgemm_kernel<64,64,8,4,4,0><<<grid, 256>>>(SEQL, XPWP, DI, DI,
            (const float*)p_xs, (const float*)p_wpad, nullptr, (float*)p_xdbl);
    }

    // 4) delta = softplus(x_dbl[:, :48] @ dt_proj_w + dt_proj_b) -> d_delta
    {
        dim3 grid(DI / 128, SEQL / 128);
        sgemm_kernel<128,128,8,8,8,1><<<grid, 256>>>(SEQL, DI, DR, XPWP,
            (const float*)p_xdbl, dt_proj_w, dt_proj_b, (float*)p_delta);
    }

    // 5) scan pass 1: per-chunk partial states
    {
        dim3 grid(DI / 256, NCH);
        scan_pass1_kernel<<<grid, 256>>>(a_log);
    }

    // 6) scan pass 2: sequential chunk combine
    scan_combine_kernel<<<(DI * DS + 255) / 256, 256>>>(a_log);

    // 7) scan pass 3: replay with correct h_in, y, u*D, SiLU(res) gating
    {
        dim3 grid(DI / 256, NCH);
        scan_pass3_kernel<<<grid, 256>>>(a_log, d_param);
    }

    // 8) out_proj: [2048,1536] @ [1536,768] -> out
    {
        dim3 grid(DM / 128, SEQL / 128);
        sgemm_kernel<128,128,8,8,8,0><<<grid, 256>>>(SEQL, DM, DI, DI,
            (const float*)p_gated, out_proj_w, nullptr, out);
    }
}

// round 5
// speedup vs baseline: 2.7493x; 2.7493x over previous
#include <cuda_runtime.h>
#include <math.h>
#include <stdint.h>

// Problem constants
#define DM   768     // d_model
#define DI   1536    // d_inner
#define DR   48      // dt_rank
#define DS   16      // d_state
#define SEQL 2048    // L
#define XPW  80      // DT_RANK + 2*D_STATE
#define XPWP 128     // padded width
#define LCH  32      // chunk length
#define NCH  64      // number of chunks
#define XSPLIT 8     // split-K factor for x_proj GEMM
#define OSPLIT 2     // split-K factor for out_proj GEMM

// ---------------- scratch (device globals; no allocation allowed) ----------
__device__ float d_xr[SEQL * 2 * DI];        // in_proj output [L, 3072]
__device__ float d_xs[SEQL * DI];            // conv+silu output (u)
__device__ float d_xprojw_pad[DI * XPWP];    // x_proj_w padded to 128 cols
__device__ float d_xdbl[SEQL * XPWP];        // x_dbl padded [L, 128]
__device__ float d_part[XSPLIT * SEQL * XPWP]; // split-K partials for x_proj
__device__ float d_opart[OSPLIT * SEQL * DM];  // split-K partials for out_proj
__device__ float d_delta[SEQL * DI];         // softplus(dt) [L, 1536]
__device__ float d_S[NCH * DI];              // per-chunk delta sums
__device__ float d_hpart[NCH * DI * DS];     // per-chunk partial final states
__device__ float d_hin[NCH * DI * DS];       // per-chunk incoming states
__device__ float d_gated[SEQL * DI];         // (scan_out + u*D) * silu(res)

// ---------------- tf32 helpers ---------------------------------------------
__device__ __forceinline__ uint32_t f2tf32(float x) {
    uint32_t y;
    asm("cvt.rna.tf32.f32 %0, %1;" : "=r"(y) : "f"(x));
    return y;
}

__device__ __forceinline__ void mma_tf32(float* c, const uint32_t* a, const uint32_t* b) {
    asm volatile(
        "mma.sync.aligned.m16n8k8.row.col.f32.tf32.tf32.f32 "
        "{%0,%1,%2,%3}, {%4,%5,%6,%7}, {%8,%9}, {%0,%1,%2,%3};"
        : "+f"(c[0]), "+f"(c[1]), "+f"(c[2]), "+f"(c[3])
        : "r"(a[0]), "r"(a[1]), "r"(a[2]), "r"(a[3]), "r"(b[0]), "r"(b[1]));
}

// ---------------- tf32 tensor-core GEMM -------------------------------------
// C[M,N] = A[M,K] * B[K,N], row-major. BM=BN=128, BK=16, 256 threads (8 warps).
// Warp layout 4x2 (M x N): warp tile 32x64 -> 2x8 mma tiles of m16n8k8.
// MODE 0: plain store. MODE 1: +bias then softplus.
// SPLITK>1: blockIdx.z selects K-chunk; C treated as [SPLITK][M][ldc] partials.
#define GBK 16
#define SAS (GBK + 4)    // A smem row stride (floats) -> conflict-free frags
#define SBS (128 + 8)    // B smem row stride

template<int MODE, int SPLITK>
__global__ __launch_bounds__(256)
void mma_gemm(int M, int N, int K, int lda, int ldb, int ldc,
              const float* __restrict__ A,
              const float* __restrict__ B,
              const float* __restrict__ bias,
              float* __restrict__ C)
{
    __shared__ uint32_t sA[2][128 * SAS];
    __shared__ uint32_t sB[2][GBK * SBS];

    const int tid  = threadIdx.x;
    const int lane = tid & 31;
    const int warp = tid >> 5;
    const int warp_m = warp >> 1;     // 0..3
    const int warp_n = warp & 1;      // 0..1
    const int g   = lane >> 2;        // groupID 0..7
    const int tig = lane & 3;         // 0..3

    const int bx = blockIdx.x, by = blockIdx.y, bz = blockIdx.z;
    const int Kc = K / SPLITK;
    const int kstart = bz * Kc;
    const int tiles = Kc / GBK;

    const float* Ag = A + (size_t)by * 128 * lda + kstart;
    const float* Bg = B + (size_t)kstart * ldb + bx * 128;
    float* Cb = C + (size_t)bz * M * ldc;

    float acc[2][8][4];
#pragma unroll
    for (int mm = 0; mm < 2; mm++)
#pragma unroll
        for (int nn = 0; nn < 8; nn++)
#pragma unroll
            for (int q = 0; q < 4; q++) acc[mm][nn][q] = 0.f;

    constexpr int AF4 = (128 * GBK / 4) / 256;   // 2
    constexpr int BF4 = (GBK * 128 / 4) / 256;   // 2
    float4 ar[AF4], br[BF4];

    // prologue load tile 0
#pragma unroll
    for (int i = 0; i < AF4; i++) {
        int idx = tid + i * 256;
        int row = idx / (GBK / 4), c4 = idx % (GBK / 4);
        ar[i] = *reinterpret_cast<const float4*>(Ag + (size_t)row * lda + c4 * 4);
    }
#pragma unroll
    for (int i = 0; i < BF4; i++) {
        int idx = tid + i * 256;
        int row = idx / 32, c4 = idx % 32;
        br[i] = *reinterpret_cast<const float4*>(Bg + (size_t)row * ldb + c4 * 4);
    }
#pragma unroll
    for (int i = 0; i < AF4; i++) {
        int idx = tid + i * 256;
        int row = idx / (GBK / 4), c4 = idx % (GBK / 4);
        uint4 v = make_uint4(f2tf32(ar[i].x), f2tf32(ar[i].y), f2tf32(ar[i].z), f2tf32(ar[i].w));
        *reinterpret_cast<uint4*>(&sA[0][row * SAS + c4 * 4]) = v;
    }
#pragma unroll
    for (int i = 0; i < BF4; i++) {
        int idx = tid + i * 256;
        int row = idx / 32, c4 = idx % 32;
        uint4 v = make_uint4(f2tf32(br[i].x), f2tf32(br[i].y), f2tf32(br[i].z), f2tf32(br[i].w));
        *reinterpret_cast<uint4*>(&sB[0][row * SBS + c4 * 4]) = v;
    }
    __syncthreads();

    for (int t = 0; t < tiles; t++) {
        if (t + 1 < tiles) {
            const float* Agt = Ag + (t + 1) * GBK;
            const float* Bgt = Bg + (size_t)(t + 1) * GBK * ldb;
#pragma unroll
            for (int i = 0; i < AF4; i++) {
                int idx = tid + i * 256;
                int row = idx / (GBK / 4), c4 = idx % (GBK / 4);
                ar[i] = *reinterpret_cast<const float4*>(Agt + (size_t)row * lda + c4 * 4);
            }
#pragma unroll
            for (int i = 0; i < BF4; i++) {
                int idx = tid + i * 256;
                int row = idx / 32, c4 = idx % 32;
                br[i] = *reinterpret_cast<const float4*>(Bgt + (size_t)row * ldb + c4 * 4);
            }
        }

        const uint32_t* pA = sA[t & 1];
        const uint32_t* pB = sB[t & 1];
#pragma unroll
        for (int ks = 0; ks < GBK / 8; ks++) {
            const int k0 = ks * 8;
            uint32_t afr[2][4], bfr[8][2];
#pragma unroll
            for (int mm = 0; mm < 2; mm++) {
                int r0 = warp_m * 32 + mm * 16;
                afr[mm][0] = pA[(r0 + g) * SAS + k0 + tig];
                afr[mm][1] = pA[(r0 + g + 8) * SAS + k0 + tig];
                afr[mm][2] = pA[(r0 + g) * SAS + k0 + tig + 4];
                afr[mm][3] = pA[(r0 + g + 8) * SAS + k0 + tig + 4];
            }
#pragma unroll
            for (int nn = 0; nn < 8; nn++) {
                int cc = warp_n * 64 + nn * 8 + g;
                bfr[nn][0] = pB[(k0 + tig) * SBS + cc];
                bfr[nn][1] = pB[(k0 + tig + 4) * SBS + cc];
            }
#pragma unroll
            for (int mm = 0; mm < 2; mm++)
#pragma unroll
                for (int nn = 0; nn < 8; nn++)
                    mma_tf32(acc[mm][nn], afr[mm], bfr[nn]);
        }

        if (t + 1 < tiles) {
            uint32_t* nA = sA[(t + 1) & 1];
            uint32_t* nB = sB[(t + 1) & 1];
#pragma unroll
            for (int i = 0; i < AF4; i++) {
                int idx = tid + i * 256;
                int row = idx / (GBK / 4), c4 = idx % (GBK / 4);
                uint4 v = make_uint4(f2tf32(ar[i].x), f2tf32(ar[i].y), f2tf32(ar[i].z), f2tf32(ar[i].w));
                *reinterpret_cast<uint4*>(&nA[row * SAS + c4 * 4]) = v;
            }
#pragma unroll
            for (int i = 0; i < BF4; i++) {
                int idx = tid + i * 256;
                int row = idx / 32, c4 = idx % 32;
                uint4 v = make_uint4(f2tf32(br[i].x), f2tf32(br[i].y), f2tf32(br[i].z), f2tf32(br[i].w));
                *reinterpret_cast<uint4*>(&nB[row * SBS + c4 * 4]) = v;
            }
            __syncthreads();
        }
    }

    // epilogue
#pragma unroll
    for (int mm = 0; mm < 2; mm++) {
#pragma unroll
        for (int nn = 0; nn < 8; nn++) {
            int row0 = by * 128 + warp_m * 32 + mm * 16 + g;
            int col  = bx * 128 + warp_n * 64 + nn * 8 + tig * 2;
            float v[4] = {acc[mm][nn][0], acc[mm][nn][1], acc[mm][nn][2], acc[mm][nn][3]};
            if (MODE == 1) {
                float b0 = bias[col], b1 = bias[col + 1];
                v[0] += b0; v[1] += b1; v[2] += b0; v[3] += b1;
#pragma unroll
                for (int q = 0; q < 4; q++)
                    v[q] = (v[q] > 20.f) ? v[q] : log1pf(expf(v[q]));
            }
            *reinterpret_cast<float2*>(Cb + (size_t)row0 * ldc + col) = make_float2(v[0], v[1]);
            *reinterpret_cast<float2*>(Cb + (size_t)(row0 + 8) * ldc + col) = make_float2(v[2], v[3]);
        }
    }
}

// ---------------- split-K reduce for x_proj ---------------------------------
__global__ void reduce_xdbl_kernel()
{
    int idx = blockIdx.x * blockDim.x + threadIdx.x;
    if (idx >= SEQL * XPWP) return;
    float s = 0.f;
#pragma unroll
    for (int z = 0; z < XSPLIT; z++)
        s += d_part[(size_t)z * SEQL * XPWP + idx];
    d_xdbl[idx] = s;
}

// ---------------- split-K reduce for out_proj --------------------------------
__global__ void reduce_out_kernel(float* __restrict__ out)
{
    int idx = blockIdx.x * blockDim.x + threadIdx.x;
    if (idx >= SEQL * DM) return;
    float s = 0.f;
#pragma unroll
    for (int z = 0; z < OSPLIT; z++)
        s += d_opart[(size_t)z * SEQL * DM + idx];
    out[idx] = s;
}

// ---------------- pad x_proj_w to 128 cols ----------------------------------
__global__ void pad_xprojw_kernel(const float* __restrict__ w)
{
    int idx = blockIdx.x * blockDim.x + threadIdx.x;
    if (idx >= DI * XPWP) return;
    int k = idx / XPWP, j = idx % XPWP;
    d_xprojw_pad[idx] = (j < XPW) ? w[k * XPW + j] : 0.f;
}

// ---------------- depthwise causal conv (k=4) + bias + SiLU -----------------
__global__ void conv_silu_kernel(const float* __restrict__ conv_w,
                                 const float* __restrict__ conv_b)
{
    int idx = blockIdx.x * blockDim.x + threadIdx.x;
    if (idx >= SEQL * DI) return;
    int d = idx % DI;
    int l = idx / DI;
    float acc = conv_b[d];
#pragma unroll
    for (int j = 0; j < 4; j++) {
        int ls = l - 3 + j;
        if (ls >= 0)
            acc = fmaf(conv_w[j * DI + d], d_xr[(size_t)ls * (2 * DI) + d], acc);
    }
    d_xs[idx] = acc / (1.f + __expf(-acc));
}

// ---------------- scan pass 1: per-chunk partial states ---------------------
__global__ __launch_bounds__(256) void scan_pass1_kernel(const float* __restrict__ a_log)
{
    const int d  = blockIdx.x * 256 + threadIdx.x;
    const int ck = blockIdx.y;
    const int l0 = ck * LCH;

    __shared__ __align__(16) float s_b[LCH * DS];
    for (int i = threadIdx.x; i < LCH * DS; i += 256) {
        int r = i >> 4, n = i & 15;
        s_b[i] = d_xdbl[(size_t)(l0 + r) * XPWP + DR + n];
    }
    __syncthreads();

    float aN[DS];
#pragma unroll
    for (int n = 0; n < DS; n++) aN[n] = -expf(a_log[d * DS + n]);

    float h[DS];
#pragma unroll
    for (int n = 0; n < DS; n++) h[n] = 0.f;
    float Ssum = 0.f;

    for (int l = l0; l < l0 + LCH; l++) {
        float dl = d_delta[(size_t)l * DI + d];
        float u  = d_xs[(size_t)l * DI + d];
        float du = dl * u;
        Ssum += dl;
        const float4* bp = reinterpret_cast<const float4*>(s_b + (l - l0) * DS);
        float4 q0 = bp[0], q1 = bp[1], q2 = bp[2], q3 = bp[3];
        float bb[DS] = {q0.x,q0.y,q0.z,q0.w, q1.x,q1.y,q1.z,q1.w,
                        q2.x,q2.y,q2.z,q2.w, q3.x,q3.y,q3.z,q3.w};
#pragma unroll
        for (int n = 0; n < DS; n++) {
            float e = __expf(dl * aN[n]);
            h[n] = fmaf(e, h[n], du * bb[n]);
        }
    }
    d_S[ck * DI + d] = Ssum;
    float4* hp = reinterpret_cast<float4*>(&d_hpart[((size_t)ck * DI + d) * DS]);
#pragma unroll
    for (int n = 0; n < 4; n++)
        hp[n] = make_float4(h[4*n], h[4*n+1], h[4*n+2], h[4*n+3]);
}

// ---------------- scan pass 2: sequential chunk combine ---------------------
__global__ __launch_bounds__(256) void scan_combine_kernel(const float* __restrict__ a_log)
{
    int t = blockIdx.x * 256 + threadIdx.x;
    if (t >= DI * DS) return;
    int d = t >> 4;
    float aN = -expf(a_log[t]);
    float h = 0.f;
    for (int ck = 0; ck < NCH; ck++) {
        d_hin[(size_t)ck * DI * DS + t] = h;
        float A = __expf(aN * d_S[ck * DI + d]);
        h = fmaf(A, h, d_hpart[(size_t)ck * DI * DS + t]);
    }
}

// ---------------- scan pass 3: full replay + y + gating ---------------------
__global__ __launch_bounds__(256) void scan_pass3_kernel(const float* __restrict__ a_log,
                                                         const float* __restrict__ d_param)
{
    const int d  = blockIdx.x * 256 + threadIdx.x;
    const int ck = blockIdx.y;
    const int l0 = ck * LCH;

    __shared__ __align__(16) float s_b[LCH * DS];
    __shared__ __align__(16) float s_c[LCH * DS];
    for (int i = threadIdx.x; i < LCH * DS; i += 256) {
        int r = i >> 4, n = i & 15;
        s_b[i] = d_xdbl[(size_t)(l0 + r) * XPWP + DR + n];
        s_c[i] = d_xdbl[(size_t)(l0 + r) * XPWP + DR + DS + n];
    }
    __syncthreads();

    float aN[DS];
#pragma unroll
    for (int n = 0; n < DS; n++) aN[n] = -expf(a_log[d * DS + n]);

    float h[DS];
    const float4* hp = reinterpret_cast<const float4*>(&d_hin[((size_t)ck * DI + d) * DS]);
#pragma unroll
    for (int n = 0; n < 4; n++) {
        float4 v = hp[n];
        h[4*n] = v.x; h[4*n+1] = v.y; h[4*n+2] = v.z; h[4*n+3] = v.w;
    }
    const float Dp = d_param[d];

    for (int l = l0; l < l0 + LCH; l++) {
        float dl = d_delta[(size_t)l * DI + d];
        float u  = d_xs[(size_t)l * DI + d];
        float du = dl * u;
        const float4* bp = reinterpret_cast<const float4*>(s_b + (l - l0) * DS);
        const float4* cp = reinterpret_cast<const float4*>(s_c + (l - l0) * DS);
        float4 b0 = bp[0], b1 = bp[1], b2 = bp[2], b3 = bp[3];
        float4 c0 = cp[0], c1 = cp[1], c2 = cp[2], c3 = cp[3];
        float bb[DS] = {b0.x,b0.y,b0.z,b0.w, b1.x,b1.y,b1.z,b1.w,
                        b2.x,b2.y,b2.z,b2.w, b3.x,b3.y,b3.z,b3.w};
        float cc[DS] = {c0.x,c0.y,c0.z,c0.w, c1.x,c1.y,c1.z,c1.w,
                        c2.x,c2.y,c2.z,c2.w, c3.x,c3.y,c3.z,c3.w};
        float y = 0.f;
#pragma unroll
        for (int n = 0; n < DS; n++) {
            float e = __expf(dl * aN[n]);
            h[n] = fmaf(e, h[n], du * bb[n]);
            y = fmaf(h[n], cc[n], y);
        }
        y = fmaf(u, Dp, y);
        float r = d_xr[(size_t)l * (2 * DI) + DI + d];
        float sr = r / (1.f + __expf(-r));
        d_gated[(size_t)l * DI + d] = y * sr;
    }
}

// ---------------- launch ----------------------------------------------------
extern "C" void kernel_launch(void* const* d_in, const int* in_sizes, int n_in,
                              void* d_out, int out_size)
{
    const float* x          = (const float*)d_in[0];
    const float* in_proj_w  = (const float*)d_in[1];
    const float* conv_w     = (const float*)d_in[2];
    const float* conv_b     = (const float*)d_in[3];
    const float* x_proj_w   = (const float*)d_in[4];
    const float* dt_proj_w  = (const float*)d_in[5];
    const float* dt_proj_b  = (const float*)d_in[6];
    const float* a_log      = (const float*)d_in[7];
    const float* d_param    = (const float*)d_in[8];
    const float* out_proj_w = (const float*)d_in[9];
    float* out = (float*)d_out;

    void *p_xr, *p_xs, *p_wpad, *p_xdbl, *p_part, *p_opart, *p_delta, *p_gated;
    cudaGetSymbolAddress(&p_xr,    d_xr);
    cudaGetSymbolAddress(&p_xs,    d_xs);
    cudaGetSymbolAddress(&p_wpad,  d_xprojw_pad);
    cudaGetSymbolAddress(&p_xdbl,  d_xdbl);
    cudaGetSymbolAddress(&p_part,  d_part);
    cudaGetSymbolAddress(&p_opart, d_opart);
    cudaGetSymbolAddress(&p_delta, d_delta);
    cudaGetSymbolAddress(&p_gated, d_gated);

    // 0) pad x_proj_w -> [1536,128]
    pad_xprojw_kernel<<<(DI * XPWP + 255) / 256, 256>>>(x_proj_w);

    // 1) in_proj: [2048,768] @ [768,3072] -> d_xr  (tf32 MMA)
    {
        dim3 grid((2 * DI) / 128, SEQL / 128, 1);
        mma_gemm<0, 1><<<grid, 256>>>(SEQL, 2 * DI, DM, DM, 2 * DI, 2 * DI,
            x, in_proj_w, nullptr, (float*)p_xr);
    }

    // 2) depthwise conv + SiLU -> d_xs
    conv_silu_kernel<<<(SEQL * DI + 255) / 256, 256>>>(conv_w, conv_b);

    // 3) x_dbl: [2048,1536] @ [1536,128] -> split-K partials -> reduce
    {
        dim3 grid(XPWP / 128, SEQL / 128, XSPLIT);
        mma_gemm<0, XSPLIT><<<grid, 256>>>(SEQL, XPWP, DI, DI, XPWP, XPWP,
            (const float*)p_xs, (const float*)p_wpad, nullptr, (float*)p_part);
        reduce_xdbl_kernel<<<(SEQL * XPWP + 255) / 256, 256>>>();
    }

    // 4) delta = softplus(x_dbl[:, :48] @ dt_proj_w + dt_proj_b)  (tf32 MMA)
    {
        dim3 grid(DI / 128, SEQL / 128, 1);
        mma_gemm<1, 1><<<grid, 256>>>(SEQL, DI, DR, XPWP, DI, DI,
            (const float*)p_xdbl, dt_proj_w, dt_proj_b, (float*)p_delta);
    }

    // 5) scan pass 1: per-chunk partial states
    {
        dim3 grid(DI / 256, NCH);
        scan_pass1_kernel<<<grid, 256>>>(a_log);
    }

    // 6) scan pass 2: sequential chunk combine
    scan_combine_kernel<<<(DI * DS + 255) / 256, 256>>>(a_log);

    // 7) scan pass 3: replay + y + u*D + SiLU(res) gating
    {
        dim3 grid(DI / 256, NCH);
        scan_pass3_kernel<<<grid, 256>>>(a_log, d_param);
    }

    // 8) out_proj: [2048,1536] @ [1536,768] -> split-K partials -> reduce
    {
        dim3 grid(DM / 128, SEQL / 128, OSPLIT);
        mma_gemm<0, OSPLIT><<<grid, 256>>>(SEQL, DM, DI, DI, DM, DM,
            (const float*)p_gated, out_proj_w, nullptr, (float*)p_opart);
        reduce_out_kernel<<<(SEQL * DM + 255) / 256, 256>>>(out);
    }
}